// round 14
// baseline (speedup 1.0000x reference)
#include <cuda_runtime.h>
#include <math.h>

constexpr int NN   = 50000;
constexpr int EE   = 500000;
constexpr int TT   = 3;
constexpr int RR   = 4;
constexpr int HH   = 8;
constexpr int NH_  = 128;
constexpr int LL   = 2;
constexpr int DIN_ = 166;
constexpr int MT_  = 240;

static int cdiv(int a, int b) { return (a + b - 1) / b; }

// ---------------- device scratch (no cudaMalloc allowed) ----------------
__device__ float g_h   [NN*NH_];
__device__ float g_h2  [NN*NH_];
__device__ float g_q   [NN*NH_];
__device__ float g_kn  [NN*NH_];
__device__ float g_vn  [NN*NH_];
__device__ float g_qrel[NN*RR*NH_];   // [n][r][h*16+d]
__device__ float g_agg [NN*NH_];      // un-normalized: sum_e ex * v_rel
__device__ float g_den [NN*HH];
__device__ float g_sin [MT_*NH_];
__device__ float g_t240[MT_*NH_];     // rte(time) = sin @ rteW + rteb
__device__ float g_kt  [MT_*TT*NH_];
__device__ float g_vt  [MT_*TT*NH_];
__device__ int2  g_e2  [EE];          // (src, tgt)
__device__ int   g_pk  [EE];          // (ko << 2) | r
__device__ int   g_cnt[TT], g_off[TT], g_fill[TT];
__device__ int   g_order[NN];

// ---------------- prologue kernels ----------------
__global__ __launch_bounds__(1024) void k_fused_count(const int* __restrict__ nt) {
    __shared__ int sc[TT];
    int tid = threadIdx.x;
    if (tid < TT) sc[tid] = 0;
    __syncthreads();
    for (int i = tid; i < NN; i += 1024) atomicAdd(&sc[nt[i]], 1);
    __syncthreads();
    if (tid < TT) { g_cnt[tid] = sc[tid]; g_fill[tid] = 0; }
    if (tid == 0) { g_off[0] = 0; g_off[1] = sc[0]; g_off[2] = sc[0] + sc[1]; }
}
__global__ void k_scatter(const int* __restrict__ nt) {
    int i = blockIdx.x * blockDim.x + threadIdx.x;
    if (i < NN) {
        int t = nt[i];
        int p = atomicAdd(&g_fill[t], 1);
        g_order[g_off[t] + p] = i;
    }
}
__global__ void k_sinus() {      // grid(240), block(64)
    int p = blockIdx.x, d = threadIdx.x;
    double div = exp((double)(2 * d) * (-log(10000.0) / (double)NH_));
    double v = (double)p * div;
    double s = 1.0 / sqrt((double)NH_);
    g_sin[p*NH_ + 2*d]     = (float)(sin(v) * s);
    g_sin[p*NH_ + 2*d + 1] = (float)(cos(v) * s);
}
__global__ void k_pack(const int* __restrict__ ei, const int* __restrict__ etime,
                       const int* __restrict__ et, const int* __restrict__ nt) {
    int e = blockIdx.x * blockDim.x + threadIdx.x;
    if (e >= EE) return;
    int src = ei[e], tgt = ei[EE + e];
    g_e2[e] = make_int2(src, tgt);
    g_pk[e] = ((etime[e] * TT + nt[src]) << 2) | et[e];
}

// ---------------- per-layer small kernels ----------------
__global__ void k_clear() {
    int i = blockIdx.x * blockDim.x + threadIdx.x;
    if (i < NN*32)
        reinterpret_cast<float4*>(g_agg)[i] = make_float4(0.f,0.f,0.f,0.f);
    if (i < NN*HH) g_den[i] = 0.f;
}
__global__ void k_rteproj(const float* __restrict__ rteW, const float* __restrict__ rteb) {
    int p = blockIdx.x, j = threadIdx.x;     // grid(240), block(128)
    const float* srow = g_sin + p*NH_;
    float acc = rteb[j];
    #pragma unroll 4
    for (int i = 0; i < NH_; i++) acc += srow[i] * __ldg(rteW + i*NH_ + j);
    g_t240[p*NH_ + j] = acc;
}
__global__ void k_ktvt(const float* __restrict__ kW, const float* __restrict__ vW) {
    int p = blockIdx.x, t = blockIdx.y, j = threadIdx.x;   // grid(240,3), block(128)
    const float* trow = g_t240 + p*NH_;
    const float* kw = kW + t*NH_*NH_;
    const float* vw = vW + t*NH_*NH_;
    float ak = 0.f, av = 0.f;
    #pragma unroll 4
    for (int i = 0; i < NH_; i++) {
        float tv = trow[i];
        ak += tv * __ldg(kw + i*NH_ + j);
        av += tv * __ldg(vw + i*NH_ + j);
    }
    g_kt[(p*TT + t)*NH_ + j] = ak;
    g_vt[(p*TT + t)*NH_ + j] = av;
}

// ---------------- bucket helper ----------------
__device__ __forceinline__ bool bucket_sel(int b, int& t, int& tile, int& cnt, int& off) {
    int c0 = g_cnt[0], c1 = g_cnt[1], c2 = g_cnt[2];
    int n0 = (c0+63)>>6, n1 = (c1+63)>>6, n2 = (c2+63)>>6;
    if      (b < n0)       { t=0; tile=b;       cnt=c0; off=0;     }
    else if (b < n0+n1)    { t=1; tile=b-n0;    cnt=c1; off=c0;    }
    else if (b < n0+n1+n2) { t=2; tile=b-n0-n1; cnt=c2; off=c0+c1; }
    else return false;
    return true;
}

// ---------------- type-bucketed GEMM: 128 threads, 16 rows/warp ----------------
// MODE 0: none   MODE 1: tanh
// MODE 2: (X / den) -> gelu on load, then skip-mix epilogue
template<int KD, int MODE>
__global__ __launch_bounds__(128) void typed_gemm(
    const float* __restrict__ X, const float* __restrict__ Wt,
    const float* __restrict__ Bt, float* __restrict__ OUT,
    const float* __restrict__ HIN, const float* __restrict__ SK,
    const float* __restrict__ DEN)
{
    __shared__ float xs[64*KD];
    __shared__ int rowNode[64];
    int t, tile, cnt, off;
    if (!bucket_sel(blockIdx.x, t, tile, cnt, off)) return;
    int rbase = tile*64;
    int nrows = min(64, cnt - rbase);
    int tid = threadIdx.x;
    for (int i = tid; i < 64; i += 128)
        rowNode[i] = (i < nrows) ? g_order[off + rbase + i] : -1;
    __syncthreads();
    if (KD == 128) {
        for (int i = tid; i < 64*32; i += 128) {
            int row = i >> 5, c4 = i & 31;
            int nd = rowNode[row];
            float4 v = make_float4(0.f,0.f,0.f,0.f);
            if (nd >= 0) v = reinterpret_cast<const float4*>(X)[nd*32 + c4];
            if (MODE == 2) {
                if (nd >= 0) {
                    float dn = fmaxf(__ldg(DEN + nd*HH + (c4 >> 2)), 1e-9f);
                    float inv = 1.f / dn;
                    v.x *= inv; v.y *= inv; v.z *= inv; v.w *= inv;
                }
                v.x = 0.5f*v.x*(1.f + erff(v.x*0.70710678118654752f));
                v.y = 0.5f*v.y*(1.f + erff(v.y*0.70710678118654752f));
                v.z = 0.5f*v.z*(1.f + erff(v.z*0.70710678118654752f));
                v.w = 0.5f*v.w*(1.f + erff(v.w*0.70710678118654752f));
            }
            reinterpret_cast<float4*>(xs)[i] = v;
        }
    } else {
        for (int i = tid; i < 64*KD; i += 128) {
            int row = i / KD, c = i - row*KD;
            int nd = rowNode[row];
            xs[i] = (nd >= 0) ? X[nd*KD + c] : 0.f;
        }
    }
    __syncthreads();
    const float4* W4 = reinterpret_cast<const float4*>(Wt + t*KD*NH_);
    int c4 = tid & 31;
    int r0 = (tid >> 5) * 16;          // 4 warps x 16 rows = 64
    float acc[16][4] = {};
    #pragma unroll 2
    for (int i = 0; i < KD; i++) {
        float4 w = __ldg(&W4[i*32 + c4]);
        const float* xr = xs + r0*KD + i;
        #pragma unroll
        for (int rr = 0; rr < 16; rr++) {
            float xv = xr[rr*KD];
            acc[rr][0] += xv*w.x; acc[rr][1] += xv*w.y;
            acc[rr][2] += xv*w.z; acc[rr][3] += xv*w.w;
        }
    }
    float4 bb = reinterpret_cast<const float4*>(Bt + t*NH_)[c4];
    float alpha = 0.f;
    if (MODE == 2) alpha = 1.f / (1.f + expf(-SK[t]));
    #pragma unroll
    for (int rr = 0; rr < 16; rr++) {
        int nd = rowNode[r0 + rr];
        if (nd < 0) continue;
        float4 o = make_float4(acc[rr][0]+bb.x, acc[rr][1]+bb.y,
                               acc[rr][2]+bb.z, acc[rr][3]+bb.w);
        if (MODE == 1) {
            o.x = tanhf(o.x); o.y = tanhf(o.y); o.z = tanhf(o.z); o.w = tanhf(o.w);
        }
        if (MODE == 2) {
            float4 hv = reinterpret_cast<const float4*>(HIN)[nd*32 + c4];
            float beta = 1.f - alpha;
            o.x = o.x*alpha + hv.x*beta; o.y = o.y*alpha + hv.y*beta;
            o.z = o.z*alpha + hv.z*beta; o.w = o.w*alpha + hv.w*beta;
        }
        reinterpret_cast<float4*>(OUT)[nd*32 + c4] = o;
    }
}

// ---------------- Q/K/V in one launch: blockIdx.y selects the matrix --------
__global__ __launch_bounds__(128) void typed_gemm_qkv3(
    const float* __restrict__ X,
    const float* __restrict__ qW, const float* __restrict__ qb,
    const float* __restrict__ kW, const float* __restrict__ kb,
    const float* __restrict__ vW, const float* __restrict__ vb)
{
    __shared__ float xs[64*NH_];
    __shared__ int rowNode[64];
    int s = blockIdx.y;
    const float* Wt = (s == 0) ? qW : (s == 1) ? kW : vW;
    const float* Bt = (s == 0) ? qb : (s == 1) ? kb : vb;
    float* OUT      = (s == 0) ? g_q : (s == 1) ? g_kn : g_vn;
    int t, tile, cnt, off;
    if (!bucket_sel(blockIdx.x, t, tile, cnt, off)) return;
    int rbase = tile*64;
    int nrows = min(64, cnt - rbase);
    int tid = threadIdx.x;
    for (int i = tid; i < 64; i += 128)
        rowNode[i] = (i < nrows) ? g_order[off + rbase + i] : -1;
    __syncthreads();
    for (int i = tid; i < 64*32; i += 128) {
        int row = i >> 5, c4 = i & 31;
        int nd = rowNode[row];
        float4 v = make_float4(0.f,0.f,0.f,0.f);
        if (nd >= 0) v = reinterpret_cast<const float4*>(X)[nd*32 + c4];
        reinterpret_cast<float4*>(xs)[i] = v;
    }
    __syncthreads();
    const float4* W4 = reinterpret_cast<const float4*>(Wt + t*NH_*NH_);
    int c4 = tid & 31;
    int r0 = (tid >> 5) * 16;
    float acc[16][4] = {};
    #pragma unroll 2
    for (int i = 0; i < NH_; i++) {
        float4 w = __ldg(&W4[i*32 + c4]);
        const float* xr = xs + r0*NH_ + i;
        #pragma unroll
        for (int rr = 0; rr < 16; rr++) {
            float xv = xr[rr*NH_];
            acc[rr][0] += xv*w.x; acc[rr][1] += xv*w.y;
            acc[rr][2] += xv*w.z; acc[rr][3] += xv*w.w;
        }
    }
    float4 bb = reinterpret_cast<const float4*>(Bt + t*NH_)[c4];
    #pragma unroll
    for (int rr = 0; rr < 16; rr++) {
        int nd = rowNode[r0 + rr];
        if (nd < 0) continue;
        reinterpret_cast<float4*>(OUT)[nd*32 + c4] =
            make_float4(acc[rr][0]+bb.x, acc[rr][1]+bb.y,
                        acc[rr][2]+bb.z, acc[rr][3]+bb.w);
    }
}

// qrel[n,r,h,d] = sum_f rel_att[r,h,d,f] * q[n,h,f]
// one block per 32 nodes: stage q once, compute ALL 4 relations
__global__ __launch_bounds__(128) void k_qrel(const float* __restrict__ A) {
    int tid = threadIdx.x;
    int h = tid >> 4, d = tid & 15;
    __shared__ float qs[32*NH_];
    int nb = blockIdx.x * 32;
    for (int i = tid; i < 32*32; i += 128) {
        int row = i >> 5, c = i & 31;
        float4 v = make_float4(0.f,0.f,0.f,0.f);
        if (nb + row < NN) v = reinterpret_cast<const float4*>(g_q)[(nb+row)*32 + c];
        reinterpret_cast<float4*>(qs)[i] = v;
    }
    __syncthreads();
    int lim = min(32, NN - nb);
    #pragma unroll
    for (int r = 0; r < RR; r++) {
        const float* Ap = A + ((r*HH + h)*16 + d)*16;
        float a[16];
        #pragma unroll
        for (int f = 0; f < 16; f++) a[f] = __ldg(Ap + f);
        for (int row = 0; row < lim; row++) {
            const float* qp = qs + row*NH_ + h*16;
            float acc = 0.f;
            #pragma unroll
            for (int f = 0; f < 16; f++) acc += a[f] * qp[f];
            g_qrel[((nb+row)*RR + r)*NH_ + tid] = acc;
        }
    }
}

// ---------------- fused edge pass (R9-proven single-edge version) ----------------
__global__ __launch_bounds__(256) void k_edge(const float* __restrict__ pri,
                                              const float* __restrict__ M) {
    int e = blockIdx.x*8 + (threadIdx.x >> 5);
    if (e >= EE) return;
    int lane = threadIdx.x & 31;
    int2 st = __ldg(&g_e2[e]);
    int pk  = __ldg(&g_pk[e]);
    int r = pk & 3, ko = pk >> 2;
    float4 k  = reinterpret_cast<const float4*>(g_kn)[st.x*32 + lane];
    float4 kt = reinterpret_cast<const float4*>(g_kt)[ko*32 + lane];
    float4 q  = reinterpret_cast<const float4*>(g_qrel)[(st.y*RR + r)*32 + lane];
    float dot = (k.x+kt.x)*q.x + (k.y+kt.y)*q.y + (k.z+kt.z)*q.z + (k.w+kt.w)*q.w;
    dot += __shfl_xor_sync(0xffffffffu, dot, 1);
    dot += __shfl_xor_sync(0xffffffffu, dot, 2);
    int h = lane >> 2;
    float ex = __expf(dot * __ldg(pri + r*HH + h) * 0.25f);
    if ((lane & 3) == 0)
        atomicAdd(&g_den[st.y*HH + h], ex);
    float4 va = reinterpret_cast<const float4*>(g_vn)[st.x*32 + lane];
    float4 vb = reinterpret_cast<const float4*>(g_vt)[ko*32 + lane];
    float vreg[4] = {va.x+vb.x, va.y+vb.y, va.z+vb.z, va.w+vb.w};
    const float4* M4 = reinterpret_cast<const float4*>(M) + ((r*HH + h)*16)*4 + (lane & 3);
    float4 acc = make_float4(0.f,0.f,0.f,0.f);
    int qbase = lane & ~3;
    #pragma unroll
    for (int j = 0; j < 4; j++) {
        #pragma unroll
        for (int i = 0; i < 4; i++) {
            float vd = __shfl_sync(0xffffffffu, vreg[i], qbase + j);
            float4 m = __ldg(M4 + (4*j + i)*4);
            acc.x += vd*m.x; acc.y += vd*m.y; acc.z += vd*m.z; acc.w += vd*m.w;
        }
    }
    acc.x *= ex; acc.y *= ex; acc.z *= ex; acc.w *= ex;
    float* dst = g_agg + st.y*NH_ + lane*4;
    asm volatile("red.global.add.v4.f32 [%0], {%1,%2,%3,%4};"
                 :: "l"(dst), "f"(acc.x), "f"(acc.y), "f"(acc.z), "f"(acc.w)
                 : "memory");
}

extern "C" void kernel_launch(void* const* d_in, const int* in_sizes, int n_in,
                              void* d_out, int out_size) {
    const float* node_feature = (const float*)d_in[0];
    const int*   node_type    = (const int*)  d_in[1];
    const int*   etime = (const int*)d_in[2];
    const int*   ei    = (const int*)d_in[3];
    const int*   et    = (const int*)d_in[4];
    const float* adapt_W = (const float*)d_in[5];
    const float* adapt_b = (const float*)d_in[6];
    const float* kW = (const float*)d_in[7];
    const float* kb = (const float*)d_in[8];
    const float* qW = (const float*)d_in[9];
    const float* qb = (const float*)d_in[10];
    const float* vW = (const float*)d_in[11];
    const float* vb = (const float*)d_in[12];
    const float* aW = (const float*)d_in[13];
    const float* ab = (const float*)d_in[14];
    const float* rel_att = (const float*)d_in[15];
    const float* rel_msg = (const float*)d_in[16];
    const float* rel_pri = (const float*)d_in[17];
    const float* skip = (const float*)d_in[18];
    const float* rteW = (const float*)d_in[19];
    const float* rteb = (const float*)d_in[20];
    float* out = (float*)d_out;

    float *p_h, *p_h2, *p_agg, *p_den;
    cudaGetSymbolAddress((void**)&p_h,   g_h);
    cudaGetSymbolAddress((void**)&p_h2,  g_h2);
    cudaGetSymbolAddress((void**)&p_agg, g_agg);
    cudaGetSymbolAddress((void**)&p_den, g_den);

    const int GEMM_BLKS = (NN + 63)/64 + TT - 1;

    // prologue — slot #4 (ncu-profiled) = typed_gemm_qkv3
    k_fused_count<<<1, 1024>>>(node_type);                                // 1
    k_scatter<<<cdiv(NN,256), 256>>>(node_type);                          // 2
    typed_gemm<DIN_,1><<<GEMM_BLKS, 128>>>(node_feature, adapt_W, adapt_b,
                                           p_h, nullptr, nullptr, nullptr); // 3

    const float* h_in = p_h;
    for (int l = 0; l < LL; l++) {
        const float* qW_l = qW + l*TT*NH_*NH_;
        const float* qb_l = qb + l*TT*NH_;
        const float* kW_l = kW + l*TT*NH_*NH_;
        const float* kb_l = kb + l*TT*NH_;
        const float* vW_l = vW + l*TT*NH_*NH_;
        const float* vb_l = vb + l*TT*NH_;
        const float* aW_l = aW + l*TT*NH_*NH_;
        const float* ab_l = ab + l*TT*NH_;
        const float* ratt = rel_att + l*RR*HH*256;
        const float* rmsg = rel_msg + l*RR*HH*256;
        const float* pri  = rel_pri + l*RR*HH;
        const float* sk   = skip + l*TT;
        float* h_out = (l == LL-1) ? out : p_h2;

        typed_gemm_qkv3<<<dim3(GEMM_BLKS,3), 128>>>(h_in, qW_l, qb_l,
                                                    kW_l, kb_l, vW_l, vb_l); // 4
        k_qrel<<<cdiv(NN,32), 128>>>(ratt);
        if (l == 0) {
            k_pack<<<cdiv(EE,256), 256>>>(ei, etime, et, node_type);
            k_sinus<<<MT_, 64>>>();
        }
        k_rteproj<<<MT_, 128>>>(rteW + l*NH_*NH_, rteb + l*NH_);
        k_ktvt<<<dim3(MT_, TT), 128>>>(kW_l, vW_l);
        k_clear<<<cdiv(NN*32, 256), 256>>>();
        k_edge<<<cdiv(EE,8), 256>>>(pri, rmsg);
        typed_gemm<NH_,2><<<GEMM_BLKS, 128>>>(p_agg, aW_l, ab_l, h_out,
                                              h_in, sk, p_den);

        h_in = h_out;
    }
}

// round 15
// speedup vs baseline: 1.0888x; 1.0888x over previous
#include <cuda_runtime.h>
#include <math.h>

constexpr int NN   = 50000;
constexpr int EE   = 500000;
constexpr int TT   = 3;
constexpr int RR   = 4;
constexpr int HH   = 8;
constexpr int NH_  = 128;
constexpr int LL   = 2;
constexpr int DIN_ = 166;
constexpr int MT_  = 240;

static int cdiv(int a, int b) { return (a + b - 1) / b; }

// ---------------- device scratch (no cudaMalloc allowed) ----------------
__device__ float g_h   [NN*NH_];
__device__ float g_h2  [NN*NH_];
__device__ float g_q   [NN*NH_];
__device__ float g_kn  [NN*NH_];
__device__ float g_vn  [NN*NH_];
__device__ float g_qrel[NN*RR*NH_];   // [n][r][h*16+d]
__device__ float g_agg [NN*NH_];      // un-normalized: sum_e ex * v_rel
__device__ float g_den [NN*HH];
__device__ float g_sin [MT_*NH_];
__device__ float g_t240[MT_*NH_];     // rte(time) = sin @ rteW + rteb
__device__ float g_kt  [MT_*TT*NH_];
__device__ float g_vt  [MT_*TT*NH_];
__device__ int2  g_e2  [EE];          // (src, tgt)
__device__ int   g_pk  [EE];          // (ko << 2) | r
__device__ int   g_cnt[TT], g_off[TT], g_fill[TT];
__device__ int   g_order[NN];

// ---------------- prologue kernels ----------------
__global__ __launch_bounds__(1024) void k_fused_count(const int* __restrict__ nt) {
    __shared__ int sc[TT];
    int tid = threadIdx.x;
    if (tid < TT) sc[tid] = 0;
    __syncthreads();
    for (int i = tid; i < NN; i += 1024) atomicAdd(&sc[nt[i]], 1);
    __syncthreads();
    if (tid < TT) { g_cnt[tid] = sc[tid]; g_fill[tid] = 0; }
    if (tid == 0) { g_off[0] = 0; g_off[1] = sc[0]; g_off[2] = sc[0] + sc[1]; }
}
__global__ void k_scatter(const int* __restrict__ nt) {
    int i = blockIdx.x * blockDim.x + threadIdx.x;
    if (i < NN) {
        int t = nt[i];
        int p = atomicAdd(&g_fill[t], 1);
        g_order[g_off[t] + p] = i;
    }
}
__global__ void k_sinus() {      // grid(240), block(64)
    int p = blockIdx.x, d = threadIdx.x;
    double div = exp((double)(2 * d) * (-log(10000.0) / (double)NH_));
    double v = (double)p * div;
    double s = 1.0 / sqrt((double)NH_);
    g_sin[p*NH_ + 2*d]     = (float)(sin(v) * s);
    g_sin[p*NH_ + 2*d + 1] = (float)(cos(v) * s);
}
__global__ void k_pack(const int* __restrict__ ei, const int* __restrict__ etime,
                       const int* __restrict__ et, const int* __restrict__ nt) {
    int e = blockIdx.x * blockDim.x + threadIdx.x;
    if (e >= EE) return;
    int src = ei[e], tgt = ei[EE + e];
    g_e2[e] = make_int2(src, tgt);
    g_pk[e] = ((etime[e] * TT + nt[src]) << 2) | et[e];
}

// ---------------- per-layer small kernels ----------------
__global__ void k_clear() {
    int i = blockIdx.x * blockDim.x + threadIdx.x;
    if (i < NN*32)
        reinterpret_cast<float4*>(g_agg)[i] = make_float4(0.f,0.f,0.f,0.f);
    if (i < NN*HH) g_den[i] = 0.f;
}
__global__ void k_rteproj(const float* __restrict__ rteW, const float* __restrict__ rteb) {
    int p = blockIdx.x, j = threadIdx.x;     // grid(240), block(128)
    const float* srow = g_sin + p*NH_;
    float acc = rteb[j];
    #pragma unroll 4
    for (int i = 0; i < NH_; i++) acc += srow[i] * __ldg(rteW + i*NH_ + j);
    g_t240[p*NH_ + j] = acc;
}
__global__ void k_ktvt(const float* __restrict__ kW, const float* __restrict__ vW) {
    int p = blockIdx.x, t = blockIdx.y, j = threadIdx.x;   // grid(240,3), block(128)
    const float* trow = g_t240 + p*NH_;
    const float* kw = kW + t*NH_*NH_;
    const float* vw = vW + t*NH_*NH_;
    float ak = 0.f, av = 0.f;
    #pragma unroll 4
    for (int i = 0; i < NH_; i++) {
        float tv = trow[i];
        ak += tv * __ldg(kw + i*NH_ + j);
        av += tv * __ldg(vw + i*NH_ + j);
    }
    g_kt[(p*TT + t)*NH_ + j] = ak;
    g_vt[(p*TT + t)*NH_ + j] = av;
}

// ---------------- bucket helper ----------------
__device__ __forceinline__ bool bucket_sel(int b, int& t, int& tile, int& cnt, int& off) {
    int c0 = g_cnt[0], c1 = g_cnt[1], c2 = g_cnt[2];
    int n0 = (c0+63)>>6, n1 = (c1+63)>>6, n2 = (c2+63)>>6;
    if      (b < n0)       { t=0; tile=b;       cnt=c0; off=0;     }
    else if (b < n0+n1)    { t=1; tile=b-n0;    cnt=c1; off=c0;    }
    else if (b < n0+n1+n2) { t=2; tile=b-n0-n1; cnt=c2; off=c0+c1; }
    else return false;
    return true;
}

// ---------------- type-bucketed GEMM (FFMA, R9-proven core) ----------------
// MODE 0: none   MODE 1: tanh
// MODE 2: (X / den) -> gelu on load, then skip-mix epilogue
template<int KD, int MODE>
__global__ __launch_bounds__(256) void typed_gemm(
    const float* __restrict__ X, const float* __restrict__ Wt,
    const float* __restrict__ Bt, float* __restrict__ OUT,
    const float* __restrict__ HIN, const float* __restrict__ SK,
    const float* __restrict__ DEN)
{
    __shared__ float xs[64*KD];
    __shared__ int rowNode[64];
    int t, tile, cnt, off;
    if (!bucket_sel(blockIdx.x, t, tile, cnt, off)) return;
    int rbase = tile*64;
    int nrows = min(64, cnt - rbase);
    int tid = threadIdx.x;
    for (int i = tid; i < 64; i += 256)
        rowNode[i] = (i < nrows) ? g_order[off + rbase + i] : -1;
    __syncthreads();
    if (KD == 128) {
        for (int i = tid; i < 64*32; i += 256) {
            int row = i >> 5, c4 = i & 31;
            int nd = rowNode[row];
            float4 v = make_float4(0.f,0.f,0.f,0.f);
            if (nd >= 0) v = reinterpret_cast<const float4*>(X)[nd*32 + c4];
            if (MODE == 2) {
                if (nd >= 0) {
                    float dn = fmaxf(__ldg(DEN + nd*HH + (c4 >> 2)), 1e-9f);
                    float inv = 1.f / dn;
                    v.x *= inv; v.y *= inv; v.z *= inv; v.w *= inv;
                }
                v.x = 0.5f*v.x*(1.f + erff(v.x*0.70710678118654752f));
                v.y = 0.5f*v.y*(1.f + erff(v.y*0.70710678118654752f));
                v.z = 0.5f*v.z*(1.f + erff(v.z*0.70710678118654752f));
                v.w = 0.5f*v.w*(1.f + erff(v.w*0.70710678118654752f));
            }
            reinterpret_cast<float4*>(xs)[i] = v;
        }
    } else {
        for (int i = tid; i < 64*KD; i += 256) {
            int row = i / KD, c = i - row*KD;
            int nd = rowNode[row];
            xs[i] = (nd >= 0) ? X[nd*KD + c] : 0.f;
        }
    }
    __syncthreads();
    const float4* W4 = reinterpret_cast<const float4*>(Wt + t*KD*NH_);
    int c4 = tid & 31;
    int r0 = (tid >> 5) * 8;
    float acc[8][4] = {};
    #pragma unroll 2
    for (int i = 0; i < KD; i++) {
        float4 w = __ldg(&W4[i*32 + c4]);
        const float* xr = xs + r0*KD + i;
        #pragma unroll
        for (int rr = 0; rr < 8; rr++) {
            float xv = xr[rr*KD];
            acc[rr][0] += xv*w.x; acc[rr][1] += xv*w.y;
            acc[rr][2] += xv*w.z; acc[rr][3] += xv*w.w;
        }
    }
    float4 bb = reinterpret_cast<const float4*>(Bt + t*NH_)[c4];
    float alpha = 0.f;
    if (MODE == 2) alpha = 1.f / (1.f + expf(-SK[t]));
    #pragma unroll
    for (int rr = 0; rr < 8; rr++) {
        int nd = rowNode[r0 + rr];
        if (nd < 0) continue;
        float4 o = make_float4(acc[rr][0]+bb.x, acc[rr][1]+bb.y,
                               acc[rr][2]+bb.z, acc[rr][3]+bb.w);
        if (MODE == 1) {
            o.x = tanhf(o.x); o.y = tanhf(o.y); o.z = tanhf(o.z); o.w = tanhf(o.w);
        }
        if (MODE == 2) {
            float4 hv = reinterpret_cast<const float4*>(HIN)[nd*32 + c4];
            float beta = 1.f - alpha;
            o.x = o.x*alpha + hv.x*beta; o.y = o.y*alpha + hv.y*beta;
            o.z = o.z*alpha + hv.z*beta; o.w = o.w*alpha + hv.w*beta;
        }
        reinterpret_cast<float4*>(OUT)[nd*32 + c4] = o;
    }
}

// ---------------- Q/K/V in one launch: blockIdx.y selects the matrix --------
__global__ __launch_bounds__(256) void typed_gemm_qkv3(
    const float* __restrict__ X,
    const float* __restrict__ qW, const float* __restrict__ qb,
    const float* __restrict__ kW, const float* __restrict__ kb,
    const float* __restrict__ vW, const float* __restrict__ vb)
{
    __shared__ float xs[64*NH_];
    __shared__ int rowNode[64];
    int s = blockIdx.y;
    const float* Wt = (s == 0) ? qW : (s == 1) ? kW : vW;
    const float* Bt = (s == 0) ? qb : (s == 1) ? kb : vb;
    float* OUT      = (s == 0) ? g_q : (s == 1) ? g_kn : g_vn;
    int t, tile, cnt, off;
    if (!bucket_sel(blockIdx.x, t, tile, cnt, off)) return;
    int rbase = tile*64;
    int nrows = min(64, cnt - rbase);
    int tid = threadIdx.x;
    for (int i = tid; i < 64; i += 256)
        rowNode[i] = (i < nrows) ? g_order[off + rbase + i] : -1;
    __syncthreads();
    for (int i = tid; i < 64*32; i += 256) {
        int row = i >> 5, c4 = i & 31;
        int nd = rowNode[row];
        float4 v = make_float4(0.f,0.f,0.f,0.f);
        if (nd >= 0) v = reinterpret_cast<const float4*>(X)[nd*32 + c4];
        reinterpret_cast<float4*>(xs)[i] = v;
    }
    __syncthreads();
    const float4* W4 = reinterpret_cast<const float4*>(Wt + t*NH_*NH_);
    int c4 = tid & 31;
    int r0 = (tid >> 5) * 8;
    float acc[8][4] = {};
    #pragma unroll 2
    for (int i = 0; i < NH_; i++) {
        float4 w = __ldg(&W4[i*32 + c4]);
        const float* xr = xs + r0*NH_ + i;
        #pragma unroll
        for (int rr = 0; rr < 8; rr++) {
            float xv = xr[rr*NH_];
            acc[rr][0] += xv*w.x; acc[rr][1] += xv*w.y;
            acc[rr][2] += xv*w.z; acc[rr][3] += xv*w.w;
        }
    }
    float4 bb = reinterpret_cast<const float4*>(Bt + t*NH_)[c4];
    #pragma unroll
    for (int rr = 0; rr < 8; rr++) {
        int nd = rowNode[r0 + rr];
        if (nd < 0) continue;
        reinterpret_cast<float4*>(OUT)[nd*32 + c4] =
            make_float4(acc[rr][0]+bb.x, acc[rr][1]+bb.y,
                        acc[rr][2]+bb.z, acc[rr][3]+bb.w);
    }
}

// qrel[n,r,h,d] = sum_f rel_att[r,h,d,f] * q[n,h,f]
// one block per 32 nodes: stage q once, compute ALL 4 relations
__global__ __launch_bounds__(128) void k_qrel(const float* __restrict__ A) {
    int tid = threadIdx.x;
    int h = tid >> 4, d = tid & 15;
    __shared__ float qs[32*NH_];
    int nb = blockIdx.x * 32;
    for (int i = tid; i < 32*32; i += 128) {
        int row = i >> 5, c = i & 31;
        float4 v = make_float4(0.f,0.f,0.f,0.f);
        if (nb + row < NN) v = reinterpret_cast<const float4*>(g_q)[(nb+row)*32 + c];
        reinterpret_cast<float4*>(qs)[i] = v;
    }
    __syncthreads();
    int lim = min(32, NN - nb);
    #pragma unroll
    for (int r = 0; r < RR; r++) {
        const float* Ap = A + ((r*HH + h)*16 + d)*16;
        float a[16];
        #pragma unroll
        for (int f = 0; f < 16; f++) a[f] = __ldg(Ap + f);
        for (int row = 0; row < lim; row++) {
            const float* qp = qs + row*NH_ + h*16;
            float acc = 0.f;
            #pragma unroll
            for (int f = 0; f < 16; f++) acc += a[f] * qp[f];
            g_qrel[((nb+row)*RR + r)*NH_ + tid] = acc;
        }
    }
}

// ---------------- fused edge pass ----------------
// ex = exp(pri * dot(k_edge, qrel[tgt,r]) / 4)
// den[tgt,h]   += ex    (packed: 2 x red.v4 per edge via shuffles)
// agg[tgt,h,f] += ex * sum_d v_edge[h,d] * rel_msg[r,h,d,f]
__global__ __launch_bounds__(256) void k_edge(const float* __restrict__ pri,
                                              const float* __restrict__ M) {
    int e = blockIdx.x*8 + (threadIdx.x >> 5);
    if (e >= EE) return;
    int lane = threadIdx.x & 31;
    int2 st = __ldg(&g_e2[e]);
    int pk  = __ldg(&g_pk[e]);
    int r = pk & 3, ko = pk >> 2;
    float4 k  = reinterpret_cast<const float4*>(g_kn)[st.x*32 + lane];
    float4 kt = reinterpret_cast<const float4*>(g_kt)[ko*32 + lane];
    float4 q  = reinterpret_cast<const float4*>(g_qrel)[(st.y*RR + r)*32 + lane];
    float dot = (k.x+kt.x)*q.x + (k.y+kt.y)*q.y + (k.z+kt.z)*q.z + (k.w+kt.w)*q.w;
    dot += __shfl_xor_sync(0xffffffffu, dot, 1);
    dot += __shfl_xor_sync(0xffffffffu, dot, 2);
    int h = lane >> 2;
    float ex = __expf(dot * __ldg(pri + r*HH + h) * 0.25f);
    // pack den updates: lanes 0 / 16 issue red.v4 covering heads 0-3 / 4-7
    {
        int base = lane & 16;
        float d0 = __shfl_sync(0xffffffffu, ex, base + 0);
        float d1 = __shfl_sync(0xffffffffu, ex, base + 4);
        float d2 = __shfl_sync(0xffffffffu, ex, base + 8);
        float d3 = __shfl_sync(0xffffffffu, ex, base + 12);
        if ((lane & 15) == 0) {
            float* dp = g_den + st.y*HH + (base >> 2);
            asm volatile("red.global.add.v4.f32 [%0], {%1,%2,%3,%4};"
                         :: "l"(dp), "f"(d0), "f"(d1), "f"(d2), "f"(d3)
                         : "memory");
        }
    }
    float4 va = reinterpret_cast<const float4*>(g_vn)[st.x*32 + lane];
    float4 vb = reinterpret_cast<const float4*>(g_vt)[ko*32 + lane];
    float vreg[4] = {va.x+vb.x, va.y+vb.y, va.z+vb.z, va.w+vb.w};
    const float4* M4 = reinterpret_cast<const float4*>(M) + ((r*HH + h)*16)*4 + (lane & 3);
    float4 acc = make_float4(0.f,0.f,0.f,0.f);
    int qbase = lane & ~3;
    #pragma unroll
    for (int j = 0; j < 4; j++) {
        #pragma unroll
        for (int i = 0; i < 4; i++) {
            float vd = __shfl_sync(0xffffffffu, vreg[i], qbase + j);
            float4 m = __ldg(M4 + (4*j + i)*4);
            acc.x += vd*m.x; acc.y += vd*m.y; acc.z += vd*m.z; acc.w += vd*m.w;
        }
    }
    acc.x *= ex; acc.y *= ex; acc.z *= ex; acc.w *= ex;
    float* dst = g_agg + st.y*NH_ + lane*4;
    asm volatile("red.global.add.v4.f32 [%0], {%1,%2,%3,%4};"
                 :: "l"(dst), "f"(acc.x), "f"(acc.y), "f"(acc.z), "f"(acc.w)
                 : "memory");
}

extern "C" void kernel_launch(void* const* d_in, const int* in_sizes, int n_in,
                              void* d_out, int out_size) {
    const float* node_feature = (const float*)d_in[0];
    const int*   node_type    = (const int*)  d_in[1];
    const int*   etime = (const int*)d_in[2];
    const int*   ei    = (const int*)d_in[3];
    const int*   et    = (const int*)d_in[4];
    const float* adapt_W = (const float*)d_in[5];
    const float* adapt_b = (const float*)d_in[6];
    const float* kW = (const float*)d_in[7];
    const float* kb = (const float*)d_in[8];
    const float* qW = (const float*)d_in[9];
    const float* qb = (const float*)d_in[10];
    const float* vW = (const float*)d_in[11];
    const float* vb = (const float*)d_in[12];
    const float* aW = (const float*)d_in[13];
    const float* ab = (const float*)d_in[14];
    const float* rel_att = (const float*)d_in[15];
    const float* rel_msg = (const float*)d_in[16];
    const float* rel_pri = (const float*)d_in[17];
    const float* skip = (const float*)d_in[18];
    const float* rteW = (const float*)d_in[19];
    const float* rteb = (const float*)d_in[20];
    float* out = (float*)d_out;

    float *p_h, *p_h2, *p_agg, *p_den;
    cudaGetSymbolAddress((void**)&p_h,   g_h);
    cudaGetSymbolAddress((void**)&p_h2,  g_h2);
    cudaGetSymbolAddress((void**)&p_agg, g_agg);
    cudaGetSymbolAddress((void**)&p_den, g_den);

    const int GEMM_BLKS = (NN + 63)/64 + TT - 1;

    // prologue — slot #4 (ncu-profiled) = typed_gemm_qkv3
    k_fused_count<<<1, 1024>>>(node_type);                                // 1
    k_scatter<<<cdiv(NN,256), 256>>>(node_type);                          // 2
    typed_gemm<DIN_,1><<<GEMM_BLKS, 256>>>(node_feature, adapt_W, adapt_b,
                                           p_h, nullptr, nullptr, nullptr); // 3

    const float* h_in = p_h;
    for (int l = 0; l < LL; l++) {
        const float* qW_l = qW + l*TT*NH_*NH_;
        const float* qb_l = qb + l*TT*NH_;
        const float* kW_l = kW + l*TT*NH_*NH_;
        const float* kb_l = kb + l*TT*NH_;
        const float* vW_l = vW + l*TT*NH_*NH_;
        const float* vb_l = vb + l*TT*NH_;
        const float* aW_l = aW + l*TT*NH_*NH_;
        const float* ab_l = ab + l*TT*NH_;
        const float* ratt = rel_att + l*RR*HH*256;
        const float* rmsg = rel_msg + l*RR*HH*256;
        const float* pri  = rel_pri + l*RR*HH;
        const float* sk   = skip + l*TT;
        float* h_out = (l == LL-1) ? out : p_h2;

        typed_gemm_qkv3<<<dim3(GEMM_BLKS,3), 256>>>(h_in, qW_l, qb_l,
                                                    kW_l, kb_l, vW_l, vb_l); // 4
        k_qrel<<<cdiv(NN,32), 128>>>(ratt);
        if (l == 0) {
            k_pack<<<cdiv(EE,256), 256>>>(ei, etime, et, node_type);
            k_sinus<<<MT_, 64>>>();
        }
        k_rteproj<<<MT_, 128>>>(rteW + l*NH_*NH_, rteb + l*NH_);
        k_ktvt<<<dim3(MT_, TT), 128>>>(kW_l, vW_l);
        k_clear<<<cdiv(NN*32, 256), 256>>>();
        k_edge<<<cdiv(EE,8), 256>>>(pri, rmsg);
        typed_gemm<NH_,2><<<GEMM_BLKS, 256>>>(p_agg, aW_l, ab_l, h_out,
                                              h_in, sk, p_den);

        h_in = h_out;
    }
}

// round 16
// speedup vs baseline: 1.0953x; 1.0059x over previous
#include <cuda_runtime.h>
#include <math.h>

constexpr int NN   = 50000;
constexpr int EE   = 500000;
constexpr int TT   = 3;
constexpr int RR   = 4;
constexpr int HH   = 8;
constexpr int NH_  = 128;
constexpr int LL   = 2;
constexpr int DIN_ = 166;
constexpr int MT_  = 240;
constexpr int SCB  = 512;                    // scan block size
constexpr int NSB  = (NN + SCB - 1) / SCB;   // 98 scan blocks

static int cdiv(int a, int b) { return (a + b - 1) / b; }

// ---------------- device scratch (no cudaMalloc allowed) ----------------
__device__ float g_h   [NN*NH_];
__device__ float g_h2  [NN*NH_];
__device__ float g_q   [NN*NH_];
__device__ float g_kn  [NN*NH_];
__device__ float g_vn  [NN*NH_];
__device__ float g_qrel[NN*RR*NH_];   // [n][r][h*16+d]
__device__ float g_agg [NN*NH_];      // un-normalized: sum_e ex * v_rel
__device__ float g_den [NN*HH];
__device__ float g_sin [MT_*NH_];
__device__ float g_t240[MT_*NH_];     // rte(time) = sin @ rteW + rteb
__device__ float g_kt  [MT_*TT*NH_];
__device__ float g_vt  [MT_*TT*NH_];
__device__ int2  g_e2  [EE];          // (src, tgt) sorted by tgt
__device__ int   g_pk  [EE];          // (ko << 2) | r, sorted by tgt
__device__ int   g_cnt[TT], g_off[TT], g_fill[TT];
__device__ int   g_order[NN];
// counting-sort scratch
__device__ int   g_ehist[NN];         // per-tgt degree, then reused
__device__ int   g_erow [NN];         // exclusive row offsets
__device__ int   g_efill[NN];         // per-tgt fill cursor
__device__ int   g_part [NSB];        // scan partials

// ---------------- prologue kernels ----------------
__global__ __launch_bounds__(1024) void k_fused_count(const int* __restrict__ nt) {
    __shared__ int sc[TT];
    int tid = threadIdx.x;
    if (tid < TT) sc[tid] = 0;
    __syncthreads();
    for (int i = tid; i < NN; i += 1024) atomicAdd(&sc[nt[i]], 1);
    __syncthreads();
    if (tid < TT) { g_cnt[tid] = sc[tid]; g_fill[tid] = 0; }
    if (tid == 0) { g_off[0] = 0; g_off[1] = sc[0]; g_off[2] = sc[0] + sc[1]; }
}
__global__ void k_scatter(const int* __restrict__ nt) {
    int i = blockIdx.x * blockDim.x + threadIdx.x;
    if (i < NN) {
        int t = nt[i];
        int p = atomicAdd(&g_fill[t], 1);
        g_order[g_off[t] + p] = i;
    }
}
__global__ void k_sinus() {      // grid(240), block(64)
    int p = blockIdx.x, d = threadIdx.x;
    double div = exp((double)(2 * d) * (-log(10000.0) / (double)NH_));
    double v = (double)p * div;
    double s = 1.0 / sqrt((double)NH_);
    g_sin[p*NH_ + 2*d]     = (float)(sin(v) * s);
    g_sin[p*NH_ + 2*d + 1] = (float)(cos(v) * s);
}

// ---- counting sort of edges by tgt ----
__global__ void k_ezero() {
    int i = blockIdx.x * blockDim.x + threadIdx.x;
    if (i < NN) { g_ehist[i] = 0; g_efill[i] = 0; }
}
__global__ void k_ehist(const int* __restrict__ ei) {
    int e = blockIdx.x * blockDim.x + threadIdx.x;
    if (e < EE) atomicAdd(&g_ehist[ei[EE + e]], 1);   // spread over 50k bins
}
__global__ __launch_bounds__(SCB) void k_scan1() {    // grid NSB
    __shared__ int sh[SCB];
    int i = blockIdx.x * SCB + threadIdx.x;
    sh[threadIdx.x] = (i < NN) ? g_ehist[i] : 0;
    __syncthreads();
    for (int s = SCB/2; s > 0; s >>= 1) {
        if (threadIdx.x < s) sh[threadIdx.x] += sh[threadIdx.x + s];
        __syncthreads();
    }
    if (threadIdx.x == 0) g_part[blockIdx.x] = sh[0];
}
__global__ void k_scan2() {                            // 1 thread, 98 values
    int run = 0;
    for (int b = 0; b < NSB; b++) { int v = g_part[b]; g_part[b] = run; run += v; }
}
__global__ __launch_bounds__(SCB) void k_scan3() {    // grid NSB
    __shared__ int sh[SCB];
    int i = blockIdx.x * SCB + threadIdx.x;
    int v = (i < NN) ? g_ehist[i] : 0;
    sh[threadIdx.x] = v;
    __syncthreads();
    // Hillis-Steele inclusive scan
    for (int s = 1; s < SCB; s <<= 1) {
        int add = (threadIdx.x >= s) ? sh[threadIdx.x - s] : 0;
        __syncthreads();
        sh[threadIdx.x] += add;
        __syncthreads();
    }
    if (i < NN) g_erow[i] = g_part[blockIdx.x] + sh[threadIdx.x] - v;  // exclusive
}
__global__ void k_esort(const int* __restrict__ ei, const int* __restrict__ etime,
                        const int* __restrict__ et, const int* __restrict__ nt) {
    int e = blockIdx.x * blockDim.x + threadIdx.x;
    if (e >= EE) return;
    int src = ei[e], tgt = ei[EE + e];
    int pos = g_erow[tgt] + atomicAdd(&g_efill[tgt], 1);   // spread over 50k bins
    g_e2[pos] = make_int2(src, tgt);
    g_pk[pos] = ((etime[e] * TT + nt[src]) << 2) | et[e];
}

// ---------------- per-layer small kernels ----------------
__global__ void k_clear() {
    int i = blockIdx.x * blockDim.x + threadIdx.x;
    if (i < NN*32)
        reinterpret_cast<float4*>(g_agg)[i] = make_float4(0.f,0.f,0.f,0.f);
    if (i < NN*HH) g_den[i] = 0.f;
}
__global__ void k_rteproj(const float* __restrict__ rteW, const float* __restrict__ rteb) {
    int p = blockIdx.x, j = threadIdx.x;     // grid(240), block(128)
    const float* srow = g_sin + p*NH_;
    float acc = rteb[j];
    #pragma unroll 4
    for (int i = 0; i < NH_; i++) acc += srow[i] * __ldg(rteW + i*NH_ + j);
    g_t240[p*NH_ + j] = acc;
}
__global__ void k_ktvt(const float* __restrict__ kW, const float* __restrict__ vW) {
    int p = blockIdx.x, t = blockIdx.y, j = threadIdx.x;   // grid(240,3), block(128)
    const float* trow = g_t240 + p*NH_;
    const float* kw = kW + t*NH_*NH_;
    const float* vw = vW + t*NH_*NH_;
    float ak = 0.f, av = 0.f;
    #pragma unroll 4
    for (int i = 0; i < NH_; i++) {
        float tv = trow[i];
        ak += tv * __ldg(kw + i*NH_ + j);
        av += tv * __ldg(vw + i*NH_ + j);
    }
    g_kt[(p*TT + t)*NH_ + j] = ak;
    g_vt[(p*TT + t)*NH_ + j] = av;
}

// ---------------- bucket helper ----------------
__device__ __forceinline__ bool bucket_sel(int b, int& t, int& tile, int& cnt, int& off) {
    int c0 = g_cnt[0], c1 = g_cnt[1], c2 = g_cnt[2];
    int n0 = (c0+63)>>6, n1 = (c1+63)>>6, n2 = (c2+63)>>6;
    if      (b < n0)       { t=0; tile=b;       cnt=c0; off=0;     }
    else if (b < n0+n1)    { t=1; tile=b-n0;    cnt=c1; off=c0;    }
    else if (b < n0+n1+n2) { t=2; tile=b-n0-n1; cnt=c2; off=c0+c1; }
    else return false;
    return true;
}

// ---------------- type-bucketed GEMM (FFMA, R9-proven core) ----------------
// MODE 0: none   MODE 1: tanh
// MODE 2: (X / den) -> gelu on load, then skip-mix epilogue
template<int KD, int MODE>
__global__ __launch_bounds__(256) void typed_gemm(
    const float* __restrict__ X, const float* __restrict__ Wt,
    const float* __restrict__ Bt, float* __restrict__ OUT,
    const float* __restrict__ HIN, const float* __restrict__ SK,
    const float* __restrict__ DEN)
{
    __shared__ float xs[64*KD];
    __shared__ int rowNode[64];
    int t, tile, cnt, off;
    if (!bucket_sel(blockIdx.x, t, tile, cnt, off)) return;
    int rbase = tile*64;
    int nrows = min(64, cnt - rbase);
    int tid = threadIdx.x;
    for (int i = tid; i < 64; i += 256)
        rowNode[i] = (i < nrows) ? g_order[off + rbase + i] : -1;
    __syncthreads();
    if (KD == 128) {
        for (int i = tid; i < 64*32; i += 256) {
            int row = i >> 5, c4 = i & 31;
            int nd = rowNode[row];
            float4 v = make_float4(0.f,0.f,0.f,0.f);
            if (nd >= 0) v = reinterpret_cast<const float4*>(X)[nd*32 + c4];
            if (MODE == 2) {
                if (nd >= 0) {
                    float dn = fmaxf(__ldg(DEN + nd*HH + (c4 >> 2)), 1e-9f);
                    float inv = 1.f / dn;
                    v.x *= inv; v.y *= inv; v.z *= inv; v.w *= inv;
                }
                v.x = 0.5f*v.x*(1.f + erff(v.x*0.70710678118654752f));
                v.y = 0.5f*v.y*(1.f + erff(v.y*0.70710678118654752f));
                v.z = 0.5f*v.z*(1.f + erff(v.z*0.70710678118654752f));
                v.w = 0.5f*v.w*(1.f + erff(v.w*0.70710678118654752f));
            }
            reinterpret_cast<float4*>(xs)[i] = v;
        }
    } else {
        for (int i = tid; i < 64*KD; i += 256) {
            int row = i / KD, c = i - row*KD;
            int nd = rowNode[row];
            xs[i] = (nd >= 0) ? X[nd*KD + c] : 0.f;
        }
    }
    __syncthreads();
    const float4* W4 = reinterpret_cast<const float4*>(Wt + t*KD*NH_);
    int c4 = tid & 31;
    int r0 = (tid >> 5) * 8;
    float acc[8][4] = {};
    #pragma unroll 2
    for (int i = 0; i < KD; i++) {
        float4 w = __ldg(&W4[i*32 + c4]);
        const float* xr = xs + r0*KD + i;
        #pragma unroll
        for (int rr = 0; rr < 8; rr++) {
            float xv = xr[rr*KD];
            acc[rr][0] += xv*w.x; acc[rr][1] += xv*w.y;
            acc[rr][2] += xv*w.z; acc[rr][3] += xv*w.w;
        }
    }
    float4 bb = reinterpret_cast<const float4*>(Bt + t*NH_)[c4];
    float alpha = 0.f;
    if (MODE == 2) alpha = 1.f / (1.f + expf(-SK[t]));
    #pragma unroll
    for (int rr = 0; rr < 8; rr++) {
        int nd = rowNode[r0 + rr];
        if (nd < 0) continue;
        float4 o = make_float4(acc[rr][0]+bb.x, acc[rr][1]+bb.y,
                               acc[rr][2]+bb.z, acc[rr][3]+bb.w);
        if (MODE == 1) {
            o.x = tanhf(o.x); o.y = tanhf(o.y); o.z = tanhf(o.z); o.w = tanhf(o.w);
        }
        if (MODE == 2) {
            float4 hv = reinterpret_cast<const float4*>(HIN)[nd*32 + c4];
            float beta = 1.f - alpha;
            o.x = o.x*alpha + hv.x*beta; o.y = o.y*alpha + hv.y*beta;
            o.z = o.z*alpha + hv.z*beta; o.w = o.w*alpha + hv.w*beta;
        }
        reinterpret_cast<float4*>(OUT)[nd*32 + c4] = o;
    }
}

// ---------------- Q/K/V in one launch: blockIdx.y selects the matrix --------
__global__ __launch_bounds__(256) void typed_gemm_qkv3(
    const float* __restrict__ X,
    const float* __restrict__ qW, const float* __restrict__ qb,
    const float* __restrict__ kW, const float* __restrict__ kb,
    const float* __restrict__ vW, const float* __restrict__ vb)
{
    __shared__ float xs[64*NH_];
    __shared__ int rowNode[64];
    int s = blockIdx.y;
    const float* Wt = (s == 0) ? qW : (s == 1) ? kW : vW;
    const float* Bt = (s == 0) ? qb : (s == 1) ? kb : vb;
    float* OUT      = (s == 0) ? g_q : (s == 1) ? g_kn : g_vn;
    int t, tile, cnt, off;
    if (!bucket_sel(blockIdx.x, t, tile, cnt, off)) return;
    int rbase = tile*64;
    int nrows = min(64, cnt - rbase);
    int tid = threadIdx.x;
    for (int i = tid; i < 64; i += 256)
        rowNode[i] = (i < nrows) ? g_order[off + rbase + i] : -1;
    __syncthreads();
    for (int i = tid; i < 64*32; i += 256) {
        int row = i >> 5, c4 = i & 31;
        int nd = rowNode[row];
        float4 v = make_float4(0.f,0.f,0.f,0.f);
        if (nd >= 0) v = reinterpret_cast<const float4*>(X)[nd*32 + c4];
        reinterpret_cast<float4*>(xs)[i] = v;
    }
    __syncthreads();
    const float4* W4 = reinterpret_cast<const float4*>(Wt + t*NH_*NH_);
    int c4 = tid & 31;
    int r0 = (tid >> 5) * 8;
    float acc[8][4] = {};
    #pragma unroll 2
    for (int i = 0; i < NH_; i++) {
        float4 w = __ldg(&W4[i*32 + c4]);
        const float* xr = xs + r0*NH_ + i;
        #pragma unroll
        for (int rr = 0; rr < 8; rr++) {
            float xv = xr[rr*NH_];
            acc[rr][0] += xv*w.x; acc[rr][1] += xv*w.y;
            acc[rr][2] += xv*w.z; acc[rr][3] += xv*w.w;
        }
    }
    float4 bb = reinterpret_cast<const float4*>(Bt + t*NH_)[c4];
    #pragma unroll
    for (int rr = 0; rr < 8; rr++) {
        int nd = rowNode[r0 + rr];
        if (nd < 0) continue;
        reinterpret_cast<float4*>(OUT)[nd*32 + c4] =
            make_float4(acc[rr][0]+bb.x, acc[rr][1]+bb.y,
                        acc[rr][2]+bb.z, acc[rr][3]+bb.w);
    }
}

// qrel[n,r,h,d] = sum_f rel_att[r,h,d,f] * q[n,h,f]  (R9 4-pass version)
__global__ __launch_bounds__(128) void k_qrel(const float* __restrict__ A) {
    int r = blockIdx.y, tid = threadIdx.x;
    int h = tid >> 4, d = tid & 15;
    const float* Ap = A + ((r*HH + h)*16 + d)*16;
    float a[16];
    #pragma unroll
    for (int f = 0; f < 16; f++) a[f] = __ldg(Ap + f);
    __shared__ float qs[32*NH_];
    int nb = blockIdx.x * 32;
    for (int i = tid; i < 32*32; i += 128) {
        int row = i >> 5, c = i & 31;
        float4 v = make_float4(0.f,0.f,0.f,0.f);
        if (nb + row < NN) v = reinterpret_cast<const float4*>(g_q)[(nb+row)*32 + c];
        reinterpret_cast<float4*>(qs)[i] = v;
    }
    __syncthreads();
    int lim = min(32, NN - nb);
    for (int row = 0; row < lim; row++) {
        const float* qp = qs + row*NH_ + h*16;
        float acc = 0.f;
        #pragma unroll
        for (int f = 0; f < 16; f++) acc += a[f] * qp[f];
        g_qrel[((nb+row)*RR + r)*NH_ + tid] = acc;
    }
}

// ---------------- fused edge pass (R9 body; edges sorted by tgt) --------------
__global__ __launch_bounds__(256) void k_edge(const float* __restrict__ pri,
                                              const float* __restrict__ M) {
    int e = blockIdx.x*8 + (threadIdx.x >> 5);
    if (e >= EE) return;
    int lane = threadIdx.x & 31;
    int2 st = __ldg(&g_e2[e]);
    int pk  = __ldg(&g_pk[e]);
    int r = pk & 3, ko = pk >> 2;
    float4 k  = reinterpret_cast<const float4*>(g_kn)[st.x*32 + lane];
    float4 kt = reinterpret_cast<const float4*>(g_kt)[ko*32 + lane];
    float4 q  = reinterpret_cast<const float4*>(g_qrel)[(st.y*RR + r)*32 + lane];
    float dot = (k.x+kt.x)*q.x + (k.y+kt.y)*q.y + (k.z+kt.z)*q.z + (k.w+kt.w)*q.w;
    dot += __shfl_xor_sync(0xffffffffu, dot, 1);
    dot += __shfl_xor_sync(0xffffffffu, dot, 2);
    int h = lane >> 2;
    float ex = __expf(dot * __ldg(pri + r*HH + h) * 0.25f);
    if ((lane & 3) == 0)
        atomicAdd(&g_den[st.y*HH + h], ex);
    float4 va = reinterpret_cast<const float4*>(g_vn)[st.x*32 + lane];
    float4 vb = reinterpret_cast<const float4*>(g_vt)[ko*32 + lane];
    float vreg[4] = {va.x+vb.x, va.y+vb.y, va.z+vb.z, va.w+vb.w};
    const float4* M4 = reinterpret_cast<const float4*>(M) + ((r*HH + h)*16)*4 + (lane & 3);
    float4 acc = make_float4(0.f,0.f,0.f,0.f);
    int qbase = lane & ~3;
    #pragma unroll
    for (int j = 0; j < 4; j++) {
        #pragma unroll
        for (int i = 0; i < 4; i++) {
            float vd = __shfl_sync(0xffffffffu, vreg[i], qbase + j);
            float4 m = __ldg(M4 + (4*j + i)*4);
            acc.x += vd*m.x; acc.y += vd*m.y; acc.z += vd*m.z; acc.w += vd*m.w;
        }
    }
    acc.x *= ex; acc.y *= ex; acc.z *= ex; acc.w *= ex;
    float* dst = g_agg + st.y*NH_ + lane*4;
    asm volatile("red.global.add.v4.f32 [%0], {%1,%2,%3,%4};"
                 :: "l"(dst), "f"(acc.x), "f"(acc.y), "f"(acc.z), "f"(acc.w)
                 : "memory");
}

extern "C" void kernel_launch(void* const* d_in, const int* in_sizes, int n_in,
                              void* d_out, int out_size) {
    const float* node_feature = (const float*)d_in[0];
    const int*   node_type    = (const int*)  d_in[1];
    const int*   etime = (const int*)d_in[2];
    const int*   ei    = (const int*)d_in[3];
    const int*   et    = (const int*)d_in[4];
    const float* adapt_W = (const float*)d_in[5];
    const float* adapt_b = (const float*)d_in[6];
    const float* kW = (const float*)d_in[7];
    const float* kb = (const float*)d_in[8];
    const float* qW = (const float*)d_in[9];
    const float* qb = (const float*)d_in[10];
    const float* vW = (const float*)d_in[11];
    const float* vb = (const float*)d_in[12];
    const float* aW = (const float*)d_in[13];
    const float* ab = (const float*)d_in[14];
    const float* rel_att = (const float*)d_in[15];
    const float* rel_msg = (const float*)d_in[16];
    const float* rel_pri = (const float*)d_in[17];
    const float* skip = (const float*)d_in[18];
    const float* rteW = (const float*)d_in[19];
    const float* rteb = (const float*)d_in[20];
    float* out = (float*)d_out;

    float *p_h, *p_h2, *p_agg, *p_den;
    cudaGetSymbolAddress((void**)&p_h,   g_h);
    cudaGetSymbolAddress((void**)&p_h2,  g_h2);
    cudaGetSymbolAddress((void**)&p_agg, g_agg);
    cudaGetSymbolAddress((void**)&p_den, g_den);

    const int GEMM_BLKS = (NN + 63)/64 + TT - 1;

    // prologue — slot #4 (ncu-profiled) = typed_gemm_qkv3
    k_fused_count<<<1, 1024>>>(node_type);                                // 1
    k_scatter<<<cdiv(NN,256), 256>>>(node_type);                          // 2
    typed_gemm<DIN_,1><<<GEMM_BLKS, 256>>>(node_feature, adapt_W, adapt_b,
                                           p_h, nullptr, nullptr, nullptr); // 3

    const float* h_in = p_h;
    for (int l = 0; l < LL; l++) {
        const float* qW_l = qW + l*TT*NH_*NH_;
        const float* qb_l = qb + l*TT*NH_;
        const float* kW_l = kW + l*TT*NH_*NH_;
        const float* kb_l = kb + l*TT*NH_;
        const float* vW_l = vW + l*TT*NH_*NH_;
        const float* vb_l = vb + l*TT*NH_;
        const float* aW_l = aW + l*TT*NH_*NH_;
        const float* ab_l = ab + l*TT*NH_;
        const float* ratt = rel_att + l*RR*HH*256;
        const float* rmsg = rel_msg + l*RR*HH*256;
        const float* pri  = rel_pri + l*RR*HH;
        const float* sk   = skip + l*TT;
        float* h_out = (l == LL-1) ? out : p_h2;

        typed_gemm_qkv3<<<dim3(GEMM_BLKS,3), 256>>>(h_in, qW_l, qb_l,
                                                    kW_l, kb_l, vW_l, vb_l); // 4
        k_qrel<<<dim3(cdiv(NN,32), RR), 128>>>(ratt);
        if (l == 0) {
            // counting sort of edges by tgt (spread atomics only)
            k_ezero<<<cdiv(NN,256), 256>>>();
            k_ehist<<<cdiv(EE,256), 256>>>(ei);
            k_scan1<<<NSB, SCB>>>();
            k_scan2<<<1, 1>>>();
            k_scan3<<<NSB, SCB>>>();
            k_esort<<<cdiv(EE,256), 256>>>(ei, etime, et, node_type);
            k_sinus<<<MT_, 64>>>();
        }
        k_rteproj<<<MT_, 128>>>(rteW + l*NH_*NH_, rteb + l*NH_);
        k_ktvt<<<dim3(MT_, TT), 128>>>(kW_l, vW_l);
        k_clear<<<cdiv(NN*32, 256), 256>>>();
        k_edge<<<cdiv(EE,8), 256>>>(pri, rmsg);
        typed_gemm<NH_,2><<<GEMM_BLKS, 256>>>(p_agg, aW_l, ab_l, h_out,
                                              h_in, sk, p_den);

        h_in = h_out;
    }
}

// round 17
// speedup vs baseline: 1.1065x; 1.0102x over previous
#include <cuda_runtime.h>
#include <math.h>

constexpr int NN   = 50000;
constexpr int EE   = 500000;
constexpr int TT   = 3;
constexpr int RR   = 4;
constexpr int HH   = 8;
constexpr int NH_  = 128;
constexpr int LL   = 2;
constexpr int DIN_ = 166;
constexpr int MT_  = 240;
constexpr int SCB  = 512;
constexpr int NSB  = (NN + SCB - 1) / SCB;

static int cdiv(int a, int b) { return (a + b - 1) / b; }

// ---------------- device scratch (no cudaMalloc allowed) ----------------
__device__ float g_h   [NN*NH_];
__device__ float g_h2  [NN*NH_];
__device__ float g_q   [NN*NH_];
__device__ float g_kn  [NN*NH_];
__device__ float g_vn  [NN*NH_];
__device__ float g_qrel[NN*RR*NH_];   // [n][r][h*16+d]
__device__ float g_agg [NN*NH_];
__device__ float g_den [NN*HH];
__device__ float g_sin [MT_*NH_];
__device__ float g_t240[MT_*NH_];
__device__ float g_kt  [MT_*TT*NH_];
__device__ float g_vt  [MT_*TT*NH_];
__device__ int2  g_e2  [EE];          // (src, tgt) sorted by tgt
__device__ int   g_pk  [EE];          // (ko << 2) | r, sorted by tgt
__device__ int   g_cnt[TT], g_off[TT], g_fill[TT];
__device__ int   g_order[NN];
__device__ int   g_ehist[NN];
__device__ int   g_erow [NN];
__device__ int   g_efill[NN];
__device__ int   g_part [NSB];

// ---------------- prologue kernels ----------------
__global__ __launch_bounds__(1024) void k_fused_count(const int* __restrict__ nt) {
    __shared__ int sc[TT];
    int tid = threadIdx.x;
    if (tid < TT) sc[tid] = 0;
    __syncthreads();
    for (int i = tid; i < NN; i += 1024) atomicAdd(&sc[nt[i]], 1);
    __syncthreads();
    if (tid < TT) { g_cnt[tid] = sc[tid]; g_fill[tid] = 0; }
    if (tid == 0) { g_off[0] = 0; g_off[1] = sc[0]; g_off[2] = sc[0] + sc[1]; }
}
__global__ void k_scatter(const int* __restrict__ nt) {
    int i = blockIdx.x * blockDim.x + threadIdx.x;
    if (i < NN) {
        int t = nt[i];
        int p = atomicAdd(&g_fill[t], 1);
        g_order[g_off[t] + p] = i;
    }
}
__global__ void k_sinus() {
    int p = blockIdx.x, d = threadIdx.x;
    double div = exp((double)(2 * d) * (-log(10000.0) / (double)NH_));
    double v = (double)p * div;
    double s = 1.0 / sqrt((double)NH_);
    g_sin[p*NH_ + 2*d]     = (float)(sin(v) * s);
    g_sin[p*NH_ + 2*d + 1] = (float)(cos(v) * s);
}

// ---- counting sort of edges by tgt ----
__global__ void k_ezero() {
    int i = blockIdx.x * blockDim.x + threadIdx.x;
    if (i < NN) { g_ehist[i] = 0; g_efill[i] = 0; }
}
__global__ void k_ehist(const int* __restrict__ ei) {
    int e = blockIdx.x * blockDim.x + threadIdx.x;
    if (e < EE) atomicAdd(&g_ehist[ei[EE + e]], 1);
}
__global__ __launch_bounds__(SCB) void k_scan1() {
    __shared__ int sh[SCB];
    int i = blockIdx.x * SCB + threadIdx.x;
    sh[threadIdx.x] = (i < NN) ? g_ehist[i] : 0;
    __syncthreads();
    for (int s = SCB/2; s > 0; s >>= 1) {
        if (threadIdx.x < s) sh[threadIdx.x] += sh[threadIdx.x + s];
        __syncthreads();
    }
    if (threadIdx.x == 0) g_part[blockIdx.x] = sh[0];
}
__global__ void k_scan2() {
    int run = 0;
    for (int b = 0; b < NSB; b++) { int v = g_part[b]; g_part[b] = run; run += v; }
}
__global__ __launch_bounds__(SCB) void k_scan3() {
    __shared__ int sh[SCB];
    int i = blockIdx.x * SCB + threadIdx.x;
    int v = (i < NN) ? g_ehist[i] : 0;
    sh[threadIdx.x] = v;
    __syncthreads();
    for (int s = 1; s < SCB; s <<= 1) {
        int add = (threadIdx.x >= s) ? sh[threadIdx.x - s] : 0;
        __syncthreads();
        sh[threadIdx.x] += add;
        __syncthreads();
    }
    if (i < NN) g_erow[i] = g_part[blockIdx.x] + sh[threadIdx.x] - v;
}
__global__ void k_esort(const int* __restrict__ ei, const int* __restrict__ etime,
                        const int* __restrict__ et, const int* __restrict__ nt) {
    int e = blockIdx.x * blockDim.x + threadIdx.x;
    if (e >= EE) return;
    int src = ei[e], tgt = ei[EE + e];
    int pos = g_erow[tgt] + atomicAdd(&g_efill[tgt], 1);
    g_e2[pos] = make_int2(src, tgt);
    g_pk[pos] = ((etime[e] * TT + nt[src]) << 2) | et[e];
}

// ---------------- per-layer small kernels ----------------
__global__ void k_clear() {
    int i = blockIdx.x * blockDim.x + threadIdx.x;
    if (i < NN*32)
        reinterpret_cast<float4*>(g_agg)[i] = make_float4(0.f,0.f,0.f,0.f);
    if (i < NN*HH) g_den[i] = 0.f;
}
__global__ void k_rteproj(const float* __restrict__ rteW, const float* __restrict__ rteb) {
    int p = blockIdx.x, j = threadIdx.x;
    const float* srow = g_sin + p*NH_;
    float acc = rteb[j];
    #pragma unroll 4
    for (int i = 0; i < NH_; i++) acc += srow[i] * __ldg(rteW + i*NH_ + j);
    g_t240[p*NH_ + j] = acc;
}
__global__ void k_ktvt(const float* __restrict__ kW, const float* __restrict__ vW) {
    int p = blockIdx.x, t = blockIdx.y, j = threadIdx.x;
    const float* trow = g_t240 + p*NH_;
    const float* kw = kW + t*NH_*NH_;
    const float* vw = vW + t*NH_*NH_;
    float ak = 0.f, av = 0.f;
    #pragma unroll 4
    for (int i = 0; i < NH_; i++) {
        float tv = trow[i];
        ak += tv * __ldg(kw + i*NH_ + j);
        av += tv * __ldg(vw + i*NH_ + j);
    }
    g_kt[(p*TT + t)*NH_ + j] = ak;
    g_vt[(p*TT + t)*NH_ + j] = av;
}

// ---------------- bucket helper ----------------
__device__ __forceinline__ bool bucket_sel(int b, int& t, int& tile, int& cnt, int& off) {
    int c0 = g_cnt[0], c1 = g_cnt[1], c2 = g_cnt[2];
    int n0 = (c0+63)>>6, n1 = (c1+63)>>6, n2 = (c2+63)>>6;
    if      (b < n0)       { t=0; tile=b;       cnt=c0; off=0;     }
    else if (b < n0+n1)    { t=1; tile=b-n0;    cnt=c1; off=c0;    }
    else if (b < n0+n1+n2) { t=2; tile=b-n0-n1; cnt=c2; off=c0+c1; }
    else return false;
    return true;
}

// ---------------- type-bucketed GEMM (FFMA, R9-proven core) ----------------
template<int KD, int MODE>
__global__ __launch_bounds__(256) void typed_gemm(
    const float* __restrict__ X, const float* __restrict__ Wt,
    const float* __restrict__ Bt, float* __restrict__ OUT,
    const float* __restrict__ HIN, const float* __restrict__ SK,
    const float* __restrict__ DEN)
{
    __shared__ float xs[64*KD];
    __shared__ int rowNode[64];
    int t, tile, cnt, off;
    if (!bucket_sel(blockIdx.x, t, tile, cnt, off)) return;
    int rbase = tile*64;
    int nrows = min(64, cnt - rbase);
    int tid = threadIdx.x;
    for (int i = tid; i < 64; i += 256)
        rowNode[i] = (i < nrows) ? g_order[off + rbase + i] : -1;
    __syncthreads();
    if (KD == 128) {
        for (int i = tid; i < 64*32; i += 256) {
            int row = i >> 5, c4 = i & 31;
            int nd = rowNode[row];
            float4 v = make_float4(0.f,0.f,0.f,0.f);
            if (nd >= 0) v = reinterpret_cast<const float4*>(X)[nd*32 + c4];
            if (MODE == 2) {
                if (nd >= 0) {
                    float dn = fmaxf(__ldg(DEN + nd*HH + (c4 >> 2)), 1e-9f);
                    float inv = 1.f / dn;
                    v.x *= inv; v.y *= inv; v.z *= inv; v.w *= inv;
                }
                v.x = 0.5f*v.x*(1.f + erff(v.x*0.70710678118654752f));
                v.y = 0.5f*v.y*(1.f + erff(v.y*0.70710678118654752f));
                v.z = 0.5f*v.z*(1.f + erff(v.z*0.70710678118654752f));
                v.w = 0.5f*v.w*(1.f + erff(v.w*0.70710678118654752f));
            }
            reinterpret_cast<float4*>(xs)[i] = v;
        }
    } else {
        for (int i = tid; i < 64*KD; i += 256) {
            int row = i / KD, c = i - row*KD;
            int nd = rowNode[row];
            xs[i] = (nd >= 0) ? X[nd*KD + c] : 0.f;
        }
    }
    __syncthreads();
    const float4* W4 = reinterpret_cast<const float4*>(Wt + t*KD*NH_);
    int c4 = tid & 31;
    int r0 = (tid >> 5) * 8;
    float acc[8][4] = {};
    #pragma unroll 2
    for (int i = 0; i < KD; i++) {
        float4 w = __ldg(&W4[i*32 + c4]);
        const float* xr = xs + r0*KD + i;
        #pragma unroll
        for (int rr = 0; rr < 8; rr++) {
            float xv = xr[rr*KD];
            acc[rr][0] += xv*w.x; acc[rr][1] += xv*w.y;
            acc[rr][2] += xv*w.z; acc[rr][3] += xv*w.w;
        }
    }
    float4 bb = reinterpret_cast<const float4*>(Bt + t*NH_)[c4];
    float alpha = 0.f;
    if (MODE == 2) alpha = 1.f / (1.f + expf(-SK[t]));
    #pragma unroll
    for (int rr = 0; rr < 8; rr++) {
        int nd = rowNode[r0 + rr];
        if (nd < 0) continue;
        float4 o = make_float4(acc[rr][0]+bb.x, acc[rr][1]+bb.y,
                               acc[rr][2]+bb.z, acc[rr][3]+bb.w);
        if (MODE == 1) {
            o.x = tanhf(o.x); o.y = tanhf(o.y); o.z = tanhf(o.z); o.w = tanhf(o.w);
        }
        if (MODE == 2) {
            float4 hv = reinterpret_cast<const float4*>(HIN)[nd*32 + c4];
            float beta = 1.f - alpha;
            o.x = o.x*alpha + hv.x*beta; o.y = o.y*alpha + hv.y*beta;
            o.z = o.z*alpha + hv.z*beta; o.w = o.w*alpha + hv.w*beta;
        }
        reinterpret_cast<float4*>(OUT)[nd*32 + c4] = o;
    }
}

// ---------------- Q/K/V in one launch ----------------
__global__ __launch_bounds__(256) void typed_gemm_qkv3(
    const float* __restrict__ X,
    const float* __restrict__ qW, const float* __restrict__ qb,
    const float* __restrict__ kW, const float* __restrict__ kb,
    const float* __restrict__ vW, const float* __restrict__ vb)
{
    __shared__ float xs[64*NH_];
    __shared__ int rowNode[64];
    int s = blockIdx.y;
    const float* Wt = (s == 0) ? qW : (s == 1) ? kW : vW;
    const float* Bt = (s == 0) ? qb : (s == 1) ? kb : vb;
    float* OUT      = (s == 0) ? g_q : (s == 1) ? g_kn : g_vn;
    int t, tile, cnt, off;
    if (!bucket_sel(blockIdx.x, t, tile, cnt, off)) return;
    int rbase = tile*64;
    int nrows = min(64, cnt - rbase);
    int tid = threadIdx.x;
    for (int i = tid; i < 64; i += 256)
        rowNode[i] = (i < nrows) ? g_order[off + rbase + i] : -1;
    __syncthreads();
    for (int i = tid; i < 64*32; i += 256) {
        int row = i >> 5, c4 = i & 31;
        int nd = rowNode[row];
        float4 v = make_float4(0.f,0.f,0.f,0.f);
        if (nd >= 0) v = reinterpret_cast<const float4*>(X)[nd*32 + c4];
        reinterpret_cast<float4*>(xs)[i] = v;
    }
    __syncthreads();
    const float4* W4 = reinterpret_cast<const float4*>(Wt + t*NH_*NH_);
    int c4 = tid & 31;
    int r0 = (tid >> 5) * 8;
    float acc[8][4] = {};
    #pragma unroll 2
    for (int i = 0; i < NH_; i++) {
        float4 w = __ldg(&W4[i*32 + c4]);
        const float* xr = xs + r0*NH_ + i;
        #pragma unroll
        for (int rr = 0; rr < 8; rr++) {
            float xv = xr[rr*NH_];
            acc[rr][0] += xv*w.x; acc[rr][1] += xv*w.y;
            acc[rr][2] += xv*w.z; acc[rr][3] += xv*w.w;
        }
    }
    float4 bb = reinterpret_cast<const float4*>(Bt + t*NH_)[c4];
    #pragma unroll
    for (int rr = 0; rr < 8; rr++) {
        int nd = rowNode[r0 + rr];
        if (nd < 0) continue;
        reinterpret_cast<float4*>(OUT)[nd*32 + c4] =
            make_float4(acc[rr][0]+bb.x, acc[rr][1]+bb.y,
                        acc[rr][2]+bb.z, acc[rr][3]+bb.w);
    }
}

// qrel[n,r,h,d] = sum_f rel_att[r,h,d,f] * q[n,h,f]  (R9 4-pass version)
__global__ __launch_bounds__(128) void k_qrel(const float* __restrict__ A) {
    int r = blockIdx.y, tid = threadIdx.x;
    int h = tid >> 4, d = tid & 15;
    const float* Ap = A + ((r*HH + h)*16 + d)*16;
    float a[16];
    #pragma unroll
    for (int f = 0; f < 16; f++) a[f] = __ldg(Ap + f);
    __shared__ float qs[32*NH_];
    int nb = blockIdx.x * 32;
    for (int i = tid; i < 32*32; i += 128) {
        int row = i >> 5, c = i & 31;
        float4 v = make_float4(0.f,0.f,0.f,0.f);
        if (nb + row < NN) v = reinterpret_cast<const float4*>(g_q)[(nb+row)*32 + c];
        reinterpret_cast<float4*>(qs)[i] = v;
    }
    __syncthreads();
    int lim = min(32, NN - nb);
    for (int row = 0; row < lim; row++) {
        const float* qp = qs + row*NH_ + h*16;
        float acc = 0.f;
        #pragma unroll
        for (int f = 0; f < 16; f++) acc += a[f] * qp[f];
        g_qrel[((nb+row)*RR + r)*NH_ + tid] = acc;
    }
}

// ---------------- fused edge pass: 2 sorted edges per warp, merged REDs ------
__global__ __launch_bounds__(256) void k_edge(const float* __restrict__ pri,
                                              const float* __restrict__ M) {
    int e0 = (blockIdx.x*8 + (threadIdx.x >> 5)) * 2;   // EE is even
    if (e0 >= EE) return;
    int lane = threadIdx.x & 31;
    int h = lane >> 2;
    int fg = lane & 3;
    int qb = lane & ~3;
    // batched index loads
    int2 st0 = __ldg(&g_e2[e0]);
    int2 st1 = __ldg(&g_e2[e0+1]);
    int pk0 = __ldg(&g_pk[e0]);
    int pk1 = __ldg(&g_pk[e0+1]);
    int r0 = pk0 & 3, ko0 = pk0 >> 2;
    int r1 = pk1 & 3, ko1 = pk1 >> 2;
    // batched vector gathers
    const float4* kn4 = reinterpret_cast<const float4*>(g_kn);
    const float4* vn4 = reinterpret_cast<const float4*>(g_vn);
    const float4* kt4 = reinterpret_cast<const float4*>(g_kt);
    const float4* vt4 = reinterpret_cast<const float4*>(g_vt);
    const float4* qr4 = reinterpret_cast<const float4*>(g_qrel);
    float4 k0  = kn4[st0.x*32 + lane],           k1  = kn4[st1.x*32 + lane];
    float4 kt0 = kt4[ko0*32 + lane],             kt1 = kt4[ko1*32 + lane];
    float4 q0  = qr4[(st0.y*RR + r0)*32 + lane], q1 = qr4[(st1.y*RR + r1)*32 + lane];
    float4 va0 = vn4[st0.x*32 + lane],           va1 = vn4[st1.x*32 + lane];
    float4 vb0 = vt4[ko0*32 + lane],             vb1 = vt4[ko1*32 + lane];
    // logits
    float dot0 = (k0.x+kt0.x)*q0.x + (k0.y+kt0.y)*q0.y
               + (k0.z+kt0.z)*q0.z + (k0.w+kt0.w)*q0.w;
    float dot1 = (k1.x+kt1.x)*q1.x + (k1.y+kt1.y)*q1.y
               + (k1.z+kt1.z)*q1.z + (k1.w+kt1.w)*q1.w;
    dot0 += __shfl_xor_sync(0xffffffffu, dot0, 1);
    dot1 += __shfl_xor_sync(0xffffffffu, dot1, 1);
    dot0 += __shfl_xor_sync(0xffffffffu, dot0, 2);
    dot1 += __shfl_xor_sync(0xffffffffu, dot1, 2);
    float ex0 = __expf(dot0 * __ldg(pri + r0*HH + h) * 0.25f);
    float ex1 = __expf(dot1 * __ldg(pri + r1*HH + h) * 0.25f);
    bool same = (st0.y == st1.y);
    if (fg == 0) {
        if (same) {
            atomicAdd(&g_den[st0.y*HH + h], ex0 + ex1);
        } else {
            atomicAdd(&g_den[st0.y*HH + h], ex0);
            atomicAdd(&g_den[st1.y*HH + h], ex1);
        }
    }
    // messages
    float vr0[4] = {va0.x+vb0.x, va0.y+vb0.y, va0.z+vb0.z, va0.w+vb0.w};
    float vr1[4] = {va1.x+vb1.x, va1.y+vb1.y, va1.z+vb1.z, va1.w+vb1.w};
    const float4* M0 = reinterpret_cast<const float4*>(M) + ((r0*HH + h)*16)*4 + fg;
    const float4* M1 = reinterpret_cast<const float4*>(M) + ((r1*HH + h)*16)*4 + fg;
    float4 a0 = make_float4(0.f,0.f,0.f,0.f);
    float4 a1 = make_float4(0.f,0.f,0.f,0.f);
    #pragma unroll
    for (int j = 0; j < 4; j++) {
        #pragma unroll
        for (int i = 0; i < 4; i++) {
            float vd0 = __shfl_sync(0xffffffffu, vr0[i], qb + j);
            float vd1 = __shfl_sync(0xffffffffu, vr1[i], qb + j);
            float4 m0 = __ldg(M0 + (4*j + i)*4);
            float4 m1 = __ldg(M1 + (4*j + i)*4);
            a0.x += vd0*m0.x; a0.y += vd0*m0.y; a0.z += vd0*m0.z; a0.w += vd0*m0.w;
            a1.x += vd1*m1.x; a1.y += vd1*m1.y; a1.z += vd1*m1.z; a1.w += vd1*m1.w;
        }
    }
    a0.x = a0.x*ex0; a0.y = a0.y*ex0; a0.z = a0.z*ex0; a0.w = a0.w*ex0;
    a1.x = a1.x*ex1; a1.y = a1.y*ex1; a1.z = a1.z*ex1; a1.w = a1.w*ex1;
    if (same) {
        float* d0 = g_agg + st0.y*NH_ + lane*4;
        asm volatile("red.global.add.v4.f32 [%0], {%1,%2,%3,%4};"
                     :: "l"(d0), "f"(a0.x+a1.x), "f"(a0.y+a1.y),
                        "f"(a0.z+a1.z), "f"(a0.w+a1.w) : "memory");
    } else {
        float* d0 = g_agg + st0.y*NH_ + lane*4;
        float* d1 = g_agg + st1.y*NH_ + lane*4;
        asm volatile("red.global.add.v4.f32 [%0], {%1,%2,%3,%4};"
                     :: "l"(d0), "f"(a0.x), "f"(a0.y), "f"(a0.z), "f"(a0.w) : "memory");
        asm volatile("red.global.add.v4.f32 [%0], {%1,%2,%3,%4};"
                     :: "l"(d1), "f"(a1.x), "f"(a1.y), "f"(a1.z), "f"(a1.w) : "memory");
    }
}

extern "C" void kernel_launch(void* const* d_in, const int* in_sizes, int n_in,
                              void* d_out, int out_size) {
    const float* node_feature = (const float*)d_in[0];
    const int*   node_type    = (const int*)  d_in[1];
    const int*   etime = (const int*)d_in[2];
    const int*   ei    = (const int*)d_in[3];
    const int*   et    = (const int*)d_in[4];
    const float* adapt_W = (const float*)d_in[5];
    const float* adapt_b = (const float*)d_in[6];
    const float* kW = (const float*)d_in[7];
    const float* kb = (const float*)d_in[8];
    const float* qW = (const float*)d_in[9];
    const float* qb = (const float*)d_in[10];
    const float* vW = (const float*)d_in[11];
    const float* vb = (const float*)d_in[12];
    const float* aW = (const float*)d_in[13];
    const float* ab = (const float*)d_in[14];
    const float* rel_att = (const float*)d_in[15];
    const float* rel_msg = (const float*)d_in[16];
    const float* rel_pri = (const float*)d_in[17];
    const float* skip = (const float*)d_in[18];
    const float* rteW = (const float*)d_in[19];
    const float* rteb = (const float*)d_in[20];
    float* out = (float*)d_out;

    float *p_h, *p_h2, *p_agg, *p_den;
    cudaGetSymbolAddress((void**)&p_h,   g_h);
    cudaGetSymbolAddress((void**)&p_h2,  g_h2);
    cudaGetSymbolAddress((void**)&p_agg, g_agg);
    cudaGetSymbolAddress((void**)&p_den, g_den);

    const int GEMM_BLKS = (NN + 63)/64 + TT - 1;

    // prologue — slot #4 (ncu-profiled) = typed_gemm_qkv3
    k_fused_count<<<1, 1024>>>(node_type);                                // 1
    k_scatter<<<cdiv(NN,256), 256>>>(node_type);                          // 2
    typed_gemm<DIN_,1><<<GEMM_BLKS, 256>>>(node_feature, adapt_W, adapt_b,
                                           p_h, nullptr, nullptr, nullptr); // 3

    const float* h_in = p_h;
    for (int l = 0; l < LL; l++) {
        const float* qW_l = qW + l*TT*NH_*NH_;
        const float* qb_l = qb + l*TT*NH_;
        const float* kW_l = kW + l*TT*NH_*NH_;
        const float* kb_l = kb + l*TT*NH_;
        const float* vW_l = vW + l*TT*NH_*NH_;
        const float* vb_l = vb + l*TT*NH_;
        const float* aW_l = aW + l*TT*NH_*NH_;
        const float* ab_l = ab + l*TT*NH_;
        const float* ratt = rel_att + l*RR*HH*256;
        const float* rmsg = rel_msg + l*RR*HH*256;
        const float* pri  = rel_pri + l*RR*HH;
        const float* sk   = skip + l*TT;
        float* h_out = (l == LL-1) ? out : p_h2;

        typed_gemm_qkv3<<<dim3(GEMM_BLKS,3), 256>>>(h_in, qW_l, qb_l,
                                                    kW_l, kb_l, vW_l, vb_l); // 4
        k_qrel<<<dim3(cdiv(NN,32), RR), 128>>>(ratt);
        if (l == 0) {
            k_ezero<<<cdiv(NN,256), 256>>>();
            k_ehist<<<cdiv(EE,256), 256>>>(ei);
            k_scan1<<<NSB, SCB>>>();
            k_scan2<<<1, 1>>>();
            k_scan3<<<NSB, SCB>>>();
            k_esort<<<cdiv(EE,256), 256>>>(ei, etime, et, node_type);
            k_sinus<<<MT_, 64>>>();
        }
        k_rteproj<<<MT_, 128>>>(rteW + l*NH_*NH_, rteb + l*NH_);
        k_ktvt<<<dim3(MT_, TT), 128>>>(kW_l, vW_l);
        k_clear<<<cdiv(NN*32, 256), 256>>>();
        k_edge<<<cdiv(EE,16), 256>>>(pri, rmsg);
        typed_gemm<NH_,2><<<GEMM_BLKS, 256>>>(p_agg, aW_l, ab_l, h_out,
                                              h_in, sk, p_den);

        h_in = h_out;
    }
}